// round 10
// baseline (speedup 1.0000x reference)
#include <cuda_runtime.h>
#include <cstdint>

#define S_  16
#define A_  16
#define DA_ 128
#define DS_ 128
#define H_  64
#define TB  64
#define NTHREADS 256
#define B_MAX 2048

#define H_LD 68

// packed expert image (word offsets)
#define PK_W1 0
#define PK_W2 8192
#define PK_W3 12288
#define PK_B1 20480
#define PK_B2 20544
#define PK_B3 20608
#define PK_STRIDE 20736

// SMEM byte offsets
#define SM_W1 0                          // 8192 words fragment-order
#define SM_W2 32768                      // 4096 words
#define SM_W3 49152                      // 8192 words
#define SM_H  81920                      // [64][68] = 17408 B
#define SM_B1 99328
#define SM_B2 99584
#define SM_B3 99840
#define SMEM_BYTES 100352

__device__ int g_cnt[S_];
__device__ int g_list[S_][A_];
__device__ float    g_wpack[256 * PK_STRIDE];
__device__ unsigned g_acttf[(size_t)B_MAX * A_ * DA_];

__global__ void prep_mask_kernel(const unsigned* __restrict__ rel) {
    if (threadIdx.x != 0) return;
    bool allint = true, allfloat = true;
    for (int i = 0; i < 64; i++) {
        unsigned u = rel[i];
        if (u > 1u) allint = false;
        if (!(u == 0u || u == 0x3F800000u)) allfloat = false;
    }
    int m[S_ * A_];
    if (allint) {
        const int* p = (const int*)rel;
        for (int i = 0; i < S_ * A_; i++) m[i] = (p[i] != 0);
    } else if (allfloat) {
        const float* p = (const float*)rel;
        for (int i = 0; i < S_ * A_; i++) m[i] = (p[i] != 0.0f);
    } else {
        const unsigned char* p = (const unsigned char*)rel;
        for (int i = 0; i < S_ * A_; i++) m[i] = (p[i] != 0);
    }
    for (int s = 0; s < S_; s++) {
        int c = 0;
        for (int a = 0; a < A_; a++)
            if (m[s * A_ + a]) g_list[s][c++] = a;
        g_cnt[s] = c;
    }
}

__device__ __forceinline__ unsigned f2tf(float f) {
    unsigned u;
    asm("cvt.rna.tf32.f32 %0, %1;" : "=r"(u) : "f"(f));
    return u;
}

// Pack weights into MMA B-fragment order (tf32 bits), fully coalesced via SMEM staging.
// Cell layout: uint4 cell index = (kc*NP + np)*32 + lane
//   u.x: k=kc*8+(lane&3),   n=np*16+(lane>>2)        (j=0,j2=0)
//   u.y: k=kc*8+(lane&3)+4, n=np*16+(lane>>2)        (j=1,j2=0)
//   u.z: k=kc*8+(lane&3),   n=np*16+8+(lane>>2)      (j=0,j2=1)
//   u.w: k=kc*8+(lane&3)+4, n=np*16+8+(lane>>2)      (j=1,j2=1)
__global__ void prep_wpack(const float* __restrict__ W1, const float* __restrict__ b1,
                           const float* __restrict__ W2, const float* __restrict__ b2,
                           const float* __restrict__ W3, const float* __restrict__ b3) {
    __shared__ float sbuf[8192];
    const int e = blockIdx.x;
    const int tid = threadIdx.x;
    float* dst = g_wpack + (size_t)e * PK_STRIDE;

    // ---- W1: K=128 x N=64, NP=4 ----
    {
        const float4* s = (const float4*)(W1 + (size_t)e * (DA_ * H_));
        for (int i = tid; i < 2048; i += 256) ((float4*)sbuf)[i] = s[i];
        __syncthreads();
        for (int cell = tid; cell < 2048; cell += 256) {
            int lane = cell & 31, g = cell >> 5;
            int kc = g >> 2, np = g & 3;
            int kb = kc * 8 + (lane & 3), nb = np * 16 + (lane >> 2);
            uint4 u;
            u.x = f2tf(sbuf[(kb + 0) * 64 + nb]);
            u.y = f2tf(sbuf[(kb + 4) * 64 + nb]);
            u.z = f2tf(sbuf[(kb + 0) * 64 + nb + 8]);
            u.w = f2tf(sbuf[(kb + 4) * 64 + nb + 8]);
            ((uint4*)(dst + PK_W1))[cell] = u;
        }
        __syncthreads();
    }
    // ---- W2: K=64 x N=64, NP=4 ----
    {
        const float4* s = (const float4*)(W2 + (size_t)e * (H_ * H_));
        for (int i = tid; i < 1024; i += 256) ((float4*)sbuf)[i] = s[i];
        __syncthreads();
        for (int cell = tid; cell < 1024; cell += 256) {
            int lane = cell & 31, g = cell >> 5;
            int kc = g >> 2, np = g & 3;
            int kb = kc * 8 + (lane & 3), nb = np * 16 + (lane >> 2);
            uint4 u;
            u.x = f2tf(sbuf[(kb + 0) * 64 + nb]);
            u.y = f2tf(sbuf[(kb + 4) * 64 + nb]);
            u.z = f2tf(sbuf[(kb + 0) * 64 + nb + 8]);
            u.w = f2tf(sbuf[(kb + 4) * 64 + nb + 8]);
            ((uint4*)(dst + PK_W2))[cell] = u;
        }
        __syncthreads();
    }
    // ---- W3: K=64 x N=128, NP=8 ----
    {
        const float4* s = (const float4*)(W3 + (size_t)e * (H_ * DS_));
        for (int i = tid; i < 2048; i += 256) ((float4*)sbuf)[i] = s[i];
        __syncthreads();
        for (int cell = tid; cell < 2048; cell += 256) {
            int lane = cell & 31, g = cell >> 5;
            int kc = g >> 3, np = g & 7;
            int kb = kc * 8 + (lane & 3), nb = np * 16 + (lane >> 2);
            uint4 u;
            u.x = f2tf(sbuf[(kb + 0) * 128 + nb]);
            u.y = f2tf(sbuf[(kb + 4) * 128 + nb]);
            u.z = f2tf(sbuf[(kb + 0) * 128 + nb + 8]);
            u.w = f2tf(sbuf[(kb + 4) * 128 + nb + 8]);
            ((uint4*)(dst + PK_W3))[cell] = u;
        }
    }
    if (tid < 64)        dst[PK_B1 + tid]        = b1[e * H_  + tid];
    else if (tid < 128)  dst[PK_B2 + tid - 64]   = b2[e * H_  + tid - 64];
    else if (tid < 256)  dst[PK_B3 + tid - 128]  = b3[e * DS_ + tid - 128];
}

__global__ void prep_act(const float4* __restrict__ act, int n4) {
    int i = blockIdx.x * blockDim.x + threadIdx.x;
    if (i < n4) {
        float4 v = act[i];
        uint4 u = { f2tf(v.x), f2tf(v.y), f2tf(v.z), f2tf(v.w) };
        ((uint4*)g_acttf)[i] = u;
    }
}

__device__ __forceinline__ void cpa16(uint32_t dst, const void* src) {
    asm volatile("cp.async.cg.shared.global [%0], [%1], 16;" :: "r"(dst), "l"(src));
}
#define CP_COMMIT() asm volatile("cp.async.commit_group;" ::: "memory")
#define CP_WAIT2()  asm volatile("cp.async.wait_group 2;" ::: "memory")

__device__ __forceinline__ void mma_tf32(float& d0, float& d1, float& d2, float& d3,
                                         unsigned a0, unsigned a1, unsigned a2, unsigned a3,
                                         unsigned b0, unsigned b1) {
    asm volatile(
        "mma.sync.aligned.m16n8k8.row.col.f32.tf32.tf32.f32 "
        "{%0,%1,%2,%3}, {%4,%5,%6,%7}, {%8,%9}, {%0,%1,%2,%3};"
        : "+f"(d0), "+f"(d1), "+f"(d2), "+f"(d3)
        : "r"(a0), "r"(a1), "r"(a2), "r"(a3), "r"(b0), "r"(b1));
}

// --- staging: pure linear copies from packed image (256 threads) ---
__device__ __forceinline__ void stage1(uint32_t sb, int tid, const float* src) {
    #pragma unroll
    for (int it = 0; it < 8; it++) {
        int i = tid + it * NTHREADS;              // 0..2047 chunks
        cpa16(sb + SM_W1 + i * 16, src + PK_W1 + i * 4);
    }
    if (tid < 16) cpa16(sb + SM_B1 + tid * 16, src + PK_B1 + tid * 4);
}
__device__ __forceinline__ void stage2(uint32_t sb, int tid, const float* src) {
    #pragma unroll
    for (int it = 0; it < 4; it++) {
        int i = tid + it * NTHREADS;              // 0..1023
        cpa16(sb + SM_W2 + i * 16, src + PK_W2 + i * 4);
    }
    if (tid < 16) cpa16(sb + SM_B2 + tid * 16, src + PK_B2 + tid * 4);
}
__device__ __forceinline__ void stage3(uint32_t sb, int tid, const float* src) {
    #pragma unroll
    for (int it = 0; it < 8; it++) {
        int i = tid + it * NTHREADS;              // 0..2047
        cpa16(sb + SM_W3 + i * 16, src + PK_W3 + i * 4);
    }
    if (tid < 32) cpa16(sb + SM_B3 + tid * 16, src + PK_B3 + tid * 4);
}

__global__ __launch_bounds__(NTHREADS, 2)
void expert_kernel(const float* __restrict__ state, float* __restrict__ out)
{
    extern __shared__ char smem[];
    const uint32_t sb = (uint32_t)__cvta_generic_to_shared(smem);
    const unsigned* W1u = (const unsigned*)(smem + SM_W1);
    const unsigned* W2u = (const unsigned*)(smem + SM_W2);
    const unsigned* W3u = (const unsigned*)(smem + SM_W3);
    float*    hs  = (float*)(smem + SM_H);
    const unsigned* hu = (const unsigned*)(smem + SM_H);
    const float* b1s = (const float*)(smem + SM_B1);
    const float* b2s = (const float*)(smem + SM_B2);
    const float* b3s = (const float*)(smem + SM_B3);

    const int s    = blockIdx.y;
    const int b0   = blockIdx.x * TB;
    const int tid  = threadIdx.x;
    const int lane = tid & 31;
    const int warp = tid >> 5;      // 0..7
    const int wm   = warp & 1;      // 2 warp-rows (m32)
    const int wn   = warp >> 1;     // 4 warp-cols (n16 for G1/G2, n32 for G3)
    const int r    = lane >> 2;
    const int q    = lane & 3;

    const int mrow0 = wm * 32 + r;

    float acc[2][4][4];
    #pragma unroll
    for (int mt = 0; mt < 2; mt++)
        #pragma unroll
        for (int nt = 0; nt < 4; nt++)
            #pragma unroll
            for (int c = 0; c < 4; c++) acc[mt][nt][c] = 0.0f;

    const int cnt = g_cnt[s];

    if (cnt > 0) {
        const float* src = g_wpack + (size_t)(s * A_ + g_list[s][0]) * PK_STRIDE;
        stage1(sb, tid, src); CP_COMMIT();
        stage2(sb, tid, src); CP_COMMIT();
        stage3(sb, tid, src); CP_COMMIT();
    }

    for (int j = 0; j < cnt; j++) {
        const int a = g_list[s][j];
        const float* srcn = (j + 1 < cnt)
            ? g_wpack + (size_t)(s * A_ + g_list[s][j + 1]) * PK_STRIDE : nullptr;

        CP_WAIT2();          // W1(j), b1(j) landed
        __syncthreads();     // publish W1; everyone done with h/W3 from prev iter

        // ---- GEMM1: h1 = relu(A @ W1 + b1), M64 N64 K128 (warp: m32 x n16) ----
        {
            float d[2][2][4];
            #pragma unroll
            for (int mt = 0; mt < 2; mt++)
                #pragma unroll
                for (int nt = 0; nt < 2; nt++)
                    { d[mt][nt][0]=0; d[mt][nt][1]=0; d[mt][nt][2]=0; d[mt][nt][3]=0; }

            const unsigned* a0p = g_acttf + ((size_t)(b0 + mrow0) * A_ + a) * DA_ + q;
            const unsigned* a1p = a0p + (size_t)8  * A_ * DA_;
            const unsigned* a2p = a0p + (size_t)16 * A_ * DA_;
            const unsigned* a3p = a0p + (size_t)24 * A_ * DA_;

            #pragma unroll 4
            for (int kc = 0; kc < 16; kc++) {
                const int k0 = kc * 8;
                unsigned af[2][4], bf[2][2];
                af[0][0] = a0p[k0];     af[0][1] = a1p[k0];
                af[0][2] = a0p[k0 + 4]; af[0][3] = a1p[k0 + 4];
                af[1][0] = a2p[k0];     af[1][1] = a3p[k0];
                af[1][2] = a2p[k0 + 4]; af[1][3] = a3p[k0 + 4];
                uint4 p0 = *(const uint4*)(W1u + ((kc * 4 + wn) * 32 + lane) * 4);
                bf[0][0] = p0.x; bf[0][1] = p0.y; bf[1][0] = p0.z; bf[1][1] = p0.w;
                #pragma unroll
                for (int mt = 0; mt < 2; mt++)
                    #pragma unroll
                    for (int nt = 0; nt < 2; nt++)
                        mma_tf32(d[mt][nt][0], d[mt][nt][1], d[mt][nt][2], d[mt][nt][3],
                                 af[mt][0], af[mt][1], af[mt][2], af[mt][3],
                                 bf[nt][0], bf[nt][1]);
            }
            #pragma unroll
            for (int mt = 0; mt < 2; mt++)
                #pragma unroll
                for (int nt = 0; nt < 2; nt++) {
                    int col = wn * 16 + nt * 8 + 2 * q;
                    float bb0 = b1s[col], bb1 = b1s[col + 1];
                    int row = mrow0 + mt * 16;
                    uint2 v0 = { f2tf(fmaxf(d[mt][nt][0] + bb0, 0.0f)),
                                 f2tf(fmaxf(d[mt][nt][1] + bb1, 0.0f)) };
                    uint2 v1 = { f2tf(fmaxf(d[mt][nt][2] + bb0, 0.0f)),
                                 f2tf(fmaxf(d[mt][nt][3] + bb1, 0.0f)) };
                    *(uint2*)(hs + row * H_LD + col)       = v0;
                    *(uint2*)(hs + (row + 8) * H_LD + col) = v1;
                }
        }
        __syncthreads();     // ALL warps done reading W1(j)/b1(j) before overwrite
        if (srcn) { stage1(sb, tid, srcn); }
        CP_COMMIT();
        CP_WAIT2();          // W2(j), b2(j) landed
        __syncthreads();     // publish W2; h1 visible to all warps

        // ---- GEMM2: h2 = relu(h1 @ W2 + b2), M64 N64 K64 (in-place h) ----
        {
            unsigned a2r[8][2][4];
            #pragma unroll
            for (int kc = 0; kc < 8; kc++) {
                const int k0 = kc * 8;
                #pragma unroll
                for (int mt = 0; mt < 2; mt++) {
                    const unsigned* hb = hu + (mrow0 + mt * 16) * H_LD + k0 + q;
                    a2r[kc][mt][0] = hb[0];
                    a2r[kc][mt][1] = hb[8 * H_LD];
                    a2r[kc][mt][2] = hb[4];
                    a2r[kc][mt][3] = hb[8 * H_LD + 4];
                }
            }
            __syncthreads();   // all reads of h1 done; safe to overwrite

            float d[2][2][4];
            #pragma unroll
            for (int mt = 0; mt < 2; mt++)
                #pragma unroll
                for (int nt = 0; nt < 2; nt++)
                    { d[mt][nt][0]=0; d[mt][nt][1]=0; d[mt][nt][2]=0; d[mt][nt][3]=0; }
            #pragma unroll
            for (int kc = 0; kc < 8; kc++) {
                unsigned bf[2][2];
                uint4 p0 = *(const uint4*)(W2u + ((kc * 4 + wn) * 32 + lane) * 4);
                bf[0][0] = p0.x; bf[0][1] = p0.y; bf[1][0] = p0.z; bf[1][1] = p0.w;
                #pragma unroll
                for (int mt = 0; mt < 2; mt++)
                    #pragma unroll
                    for (int nt = 0; nt < 2; nt++)
                        mma_tf32(d[mt][nt][0], d[mt][nt][1], d[mt][nt][2], d[mt][nt][3],
                                 a2r[kc][mt][0], a2r[kc][mt][1], a2r[kc][mt][2], a2r[kc][mt][3],
                                 bf[nt][0], bf[nt][1]);
            }
            #pragma unroll
            for (int mt = 0; mt < 2; mt++)
                #pragma unroll
                for (int nt = 0; nt < 2; nt++) {
                    int col = wn * 16 + nt * 8 + 2 * q;
                    float bb0 = b2s[col], bb1 = b2s[col + 1];
                    int row = mrow0 + mt * 16;
                    uint2 v0 = { f2tf(fmaxf(d[mt][nt][0] + bb0, 0.0f)),
                                 f2tf(fmaxf(d[mt][nt][1] + bb1, 0.0f)) };
                    uint2 v1 = { f2tf(fmaxf(d[mt][nt][2] + bb0, 0.0f)),
                                 f2tf(fmaxf(d[mt][nt][3] + bb1, 0.0f)) };
                    *(uint2*)(hs + row * H_LD + col)       = v0;
                    *(uint2*)(hs + (row + 8) * H_LD + col) = v1;
                }
        }
        __syncthreads();     // ALL warps done reading W2(j)/b2(j) before overwrite
        if (srcn) { stage2(sb, tid, srcn); }
        CP_COMMIT();
        CP_WAIT2();          // W3(j), b3(j) landed
        __syncthreads();     // publish W3; h2 visible to all warps

        // ---- GEMM3: acc += relu(h2 @ W3 + b3), M64 N128 K64 (warp: m32 x n32) ----
        {
            float d[2][4][4];
            #pragma unroll
            for (int mt = 0; mt < 2; mt++)
                #pragma unroll
                for (int nt = 0; nt < 4; nt++)
                    { d[mt][nt][0]=0; d[mt][nt][1]=0; d[mt][nt][2]=0; d[mt][nt][3]=0; }
            #pragma unroll 4
            for (int kc = 0; kc < 8; kc++) {
                const int k0 = kc * 8;
                unsigned af[2][4], bf[4][2];
                #pragma unroll
                for (int mt = 0; mt < 2; mt++) {
                    const unsigned* hb = hu + (mrow0 + mt * 16) * H_LD + k0 + q;
                    af[mt][0] = hb[0];
                    af[mt][1] = hb[8 * H_LD];
                    af[mt][2] = hb[4];
                    af[mt][3] = hb[8 * H_LD + 4];
                }
                #pragma unroll
                for (int pp = 0; pp < 2; pp++) {
                    uint4 p = *(const uint4*)(W3u + ((kc * 8 + wn * 2 + pp) * 32 + lane) * 4);
                    bf[2 * pp][0]     = p.x; bf[2 * pp][1]     = p.y;
                    bf[2 * pp + 1][0] = p.z; bf[2 * pp + 1][1] = p.w;
                }
                #pragma unroll
                for (int mt = 0; mt < 2; mt++)
                    #pragma unroll
                    for (int nt = 0; nt < 4; nt++)
                        mma_tf32(d[mt][nt][0], d[mt][nt][1], d[mt][nt][2], d[mt][nt][3],
                                 af[mt][0], af[mt][1], af[mt][2], af[mt][3],
                                 bf[nt][0], bf[nt][1]);
            }
            #pragma unroll
            for (int mt = 0; mt < 2; mt++)
                #pragma unroll
                for (int nt = 0; nt < 4; nt++) {
                    int col = wn * 32 + nt * 8 + 2 * q;
                    float bb0 = b3s[col], bb1 = b3s[col + 1];
                    acc[mt][nt][0] += fmaxf(d[mt][nt][0] + bb0, 0.0f);
                    acc[mt][nt][1] += fmaxf(d[mt][nt][1] + bb1, 0.0f);
                    acc[mt][nt][2] += fmaxf(d[mt][nt][2] + bb0, 0.0f);
                    acc[mt][nt][3] += fmaxf(d[mt][nt][3] + bb1, 0.0f);
                }
        }
        __syncthreads();     // ALL warps done reading W3(j)/b3(j)/h2 before overwrite
        if (srcn) { stage3(sb, tid, srcn); }
        CP_COMMIT();
    }

    // ---- epilogue: out = state + diff ----
    #pragma unroll
    for (int mt = 0; mt < 2; mt++)
        #pragma unroll
        for (int nt = 0; nt < 4; nt++) {
            int row = b0 + mrow0 + mt * 16;
            int col = wn * 32 + nt * 8 + 2 * q;
            size_t base = ((size_t)row * S_ + s) * DS_ + col;
            float2 s0 = *(const float2*)(state + base);
            float2 s1 = *(const float2*)(state + base + 8 * (size_t)S_ * DS_);
            float2 o0 = { s0.x + acc[mt][nt][0], s0.y + acc[mt][nt][1] };
            float2 o1 = { s1.x + acc[mt][nt][2], s1.y + acc[mt][nt][3] };
            *(float2*)(out + base)                        = o0;
            *(float2*)(out + base + 8 * (size_t)S_ * DS_) = o1;
        }
}

extern "C" void kernel_launch(void* const* d_in, const int* in_sizes, int n_in,
                              void* d_out, int out_size)
{
    const float* state = (const float*)d_in[0];
    const float* act   = (const float*)d_in[1];
    const void*  rel   = d_in[2];
    const float* W1 = (const float*)d_in[3];
    const float* b1 = (const float*)d_in[4];
    const float* W2 = (const float*)d_in[5];
    const float* b2 = (const float*)d_in[6];
    const float* W3 = (const float*)d_in[7];
    const float* b3 = (const float*)d_in[8];
    float* out = (float*)d_out;

    const int B = in_sizes[0] / (S_ * DS_);

    cudaFuncSetAttribute(expert_kernel,
                         cudaFuncAttributeMaxDynamicSharedMemorySize, SMEM_BYTES);

    prep_mask_kernel<<<1, 32>>>((const unsigned*)rel);
    prep_wpack<<<S_ * A_, 256>>>(W1, b1, W2, b2, W3, b3);
    {
        int n4 = B * A_ * DA_ / 4;
        prep_act<<<(n4 + 255) / 256, 256>>>((const float4*)act, n4);
    }

    dim3 grid(B / TB, S_);
    expert_kernel<<<grid, NTHREADS, SMEM_BYTES>>>(state, out);
}

// round 11
// speedup vs baseline: 2.1154x; 2.1154x over previous
#include <cuda_runtime.h>
#include <cstdint>

#define S_  16
#define A_  16
#define DA_ 128
#define DS_ 128
#define H_  64
#define TB  64
#define NTHREADS 128
#define B_MAX 2048

#define H_LD 68

// packed expert image (word offsets)
#define PK_W1 0
#define PK_W2 8192
#define PK_W3 12288
#define PK_B1 20480
#define PK_B2 20544
#define PK_B3 20608
#define PK_STRIDE 20736

// SMEM byte offsets
#define SM_W1 0
#define SM_W2 32768
#define SM_W3 49152
#define SM_H  81920
#define SM_B1 99328
#define SM_B2 99584
#define SM_B3 99840
#define SMEM_BYTES 100352

__device__ int g_cnt[S_];
__device__ int g_list[S_][A_];
__device__ int g_sperm[S_];
__device__ float    g_wpack[256 * PK_STRIDE];
__device__ unsigned g_apack[(size_t)B_MAX * A_ * DA_];   // fragment-packed A tiles

__global__ void prep_mask_kernel(const unsigned* __restrict__ rel) {
    if (threadIdx.x != 0) return;
    bool allint = true, allfloat = true;
    for (int i = 0; i < 64; i++) {
        unsigned u = rel[i];
        if (u > 1u) allint = false;
        if (!(u == 0u || u == 0x3F800000u)) allfloat = false;
    }
    int m[S_ * A_];
    if (allint) {
        const int* p = (const int*)rel;
        for (int i = 0; i < S_ * A_; i++) m[i] = (p[i] != 0);
    } else if (allfloat) {
        const float* p = (const float*)rel;
        for (int i = 0; i < S_ * A_; i++) m[i] = (p[i] != 0.0f);
    } else {
        const unsigned char* p = (const unsigned char*)rel;
        for (int i = 0; i < S_ * A_; i++) m[i] = (p[i] != 0);
    }
    int cnt[S_];
    for (int s = 0; s < S_; s++) {
        int c = 0;
        for (int a = 0; a < A_; a++)
            if (m[s * A_ + a]) g_list[s][c++] = a;
        g_cnt[s] = c;
        cnt[s] = c;
    }
    // sort s descending by cnt -> longest CTAs schedule first (tail balance)
    int perm[S_];
    for (int i = 0; i < S_; i++) perm[i] = i;
    for (int i = 0; i < S_ - 1; i++) {
        int best = i;
        for (int j = i + 1; j < S_; j++)
            if (cnt[perm[j]] > cnt[perm[best]]) best = j;
        int t = perm[i]; perm[i] = perm[best]; perm[best] = t;
    }
    for (int i = 0; i < S_; i++) g_sperm[i] = perm[i];
}

__device__ __forceinline__ unsigned f2tf(float f) {
    unsigned u;
    asm("cvt.rna.tf32.f32 %0, %1;" : "=r"(u) : "f"(f));
    return u;
}

// One merged pack kernel.
// Blocks [0,256): weight fragment packing (as R10, coalesced via SMEM staging).
// Blocks [256, 256 + nmb*A_): A fragment packing per (mblock32, a) tile.
// A tile layout (uint4 cells): cell = (kc*2 + mt)*32 + lane
//   r=lane>>2, q=lane&3, rl=mt*16+r, k=kc*8+q:
//   u = { A[rl][k], A[rl+8][k], A[rl][k+4], A[rl+8][k+4] }   (matches af[mt][0..3])
__global__ void prep_pack(const float* __restrict__ W1, const float* __restrict__ b1,
                          const float* __restrict__ W2, const float* __restrict__ b2,
                          const float* __restrict__ W3, const float* __restrict__ b3,
                          const float* __restrict__ act) {
    __shared__ float sbuf[8192];
    const int bx = blockIdx.x;
    const int tid = threadIdx.x;

    if (bx < 256) {
        const int e = bx;
        float* dst = g_wpack + (size_t)e * PK_STRIDE;
        // ---- W1: K=128 x N=64, NP=4 ----
        {
            const float4* s = (const float4*)(W1 + (size_t)e * (DA_ * H_));
            for (int i = tid; i < 2048; i += 256) ((float4*)sbuf)[i] = s[i];
            __syncthreads();
            for (int cell = tid; cell < 2048; cell += 256) {
                int lane = cell & 31, g = cell >> 5;
                int kc = g >> 2, np = g & 3;
                int kb = kc * 8 + (lane & 3), nb = np * 16 + (lane >> 2);
                uint4 u;
                u.x = f2tf(sbuf[(kb + 0) * 64 + nb]);
                u.y = f2tf(sbuf[(kb + 4) * 64 + nb]);
                u.z = f2tf(sbuf[(kb + 0) * 64 + nb + 8]);
                u.w = f2tf(sbuf[(kb + 4) * 64 + nb + 8]);
                ((uint4*)(dst + PK_W1))[cell] = u;
            }
            __syncthreads();
        }
        // ---- W2: K=64 x N=64, NP=4 ----
        {
            const float4* s = (const float4*)(W2 + (size_t)e * (H_ * H_));
            for (int i = tid; i < 1024; i += 256) ((float4*)sbuf)[i] = s[i];
            __syncthreads();
            for (int cell = tid; cell < 1024; cell += 256) {
                int lane = cell & 31, g = cell >> 5;
                int kc = g >> 2, np = g & 3;
                int kb = kc * 8 + (lane & 3), nb = np * 16 + (lane >> 2);
                uint4 u;
                u.x = f2tf(sbuf[(kb + 0) * 64 + nb]);
                u.y = f2tf(sbuf[(kb + 4) * 64 + nb]);
                u.z = f2tf(sbuf[(kb + 0) * 64 + nb + 8]);
                u.w = f2tf(sbuf[(kb + 4) * 64 + nb + 8]);
                ((uint4*)(dst + PK_W2))[cell] = u;
            }
            __syncthreads();
        }
        // ---- W3: K=64 x N=128, NP=8 ----
        {
            const float4* s = (const float4*)(W3 + (size_t)e * (H_ * DS_));
            for (int i = tid; i < 2048; i += 256) ((float4*)sbuf)[i] = s[i];
            __syncthreads();
            for (int cell = tid; cell < 2048; cell += 256) {
                int lane = cell & 31, g = cell >> 5;
                int kc = g >> 3, np = g & 7;
                int kb = kc * 8 + (lane & 3), nb = np * 16 + (lane >> 2);
                uint4 u;
                u.x = f2tf(sbuf[(kb + 0) * 128 + nb]);
                u.y = f2tf(sbuf[(kb + 4) * 128 + nb]);
                u.z = f2tf(sbuf[(kb + 0) * 128 + nb + 8]);
                u.w = f2tf(sbuf[(kb + 4) * 128 + nb + 8]);
                ((uint4*)(dst + PK_W3))[cell] = u;
            }
        }
        if (tid < 64)        dst[PK_B1 + tid]        = b1[e * H_  + tid];
        else if (tid < 128)  dst[PK_B2 + tid - 64]   = b2[e * H_  + tid - 64];
        else if (tid < 256)  dst[PK_B3 + tid - 128]  = b3[e * DS_ + tid - 128];
    } else {
        const int t = bx - 256;
        const int mb = t >> 4, a = t & 15;
        const float* srcb = act + ((size_t)(mb * 32) * A_ + a) * DA_;
        for (int i = tid; i < 1024; i += 256) {
            int row = i >> 5, c4 = i & 31;
            *(float4*)(sbuf + row * 128 + c4 * 4) =
                *(const float4*)(srcb + (size_t)row * A_ * DA_ + c4 * 4);
        }
        __syncthreads();
        unsigned* dst = g_apack + ((size_t)mb * A_ + a) * 4096;
        for (int cell = tid; cell < 1024; cell += 256) {
            int lane = cell & 31, mt = (cell >> 5) & 1, kc = cell >> 6;
            int rl = mt * 16 + (lane >> 2), k = kc * 8 + (lane & 3);
            uint4 u;
            u.x = f2tf(sbuf[rl * 128 + k]);
            u.y = f2tf(sbuf[(rl + 8) * 128 + k]);
            u.z = f2tf(sbuf[rl * 128 + k + 4]);
            u.w = f2tf(sbuf[(rl + 8) * 128 + k + 4]);
            ((uint4*)dst)[cell] = u;
        }
    }
}

__device__ __forceinline__ void cpa16(uint32_t dst, const void* src) {
    asm volatile("cp.async.cg.shared.global [%0], [%1], 16;" :: "r"(dst), "l"(src));
}
#define CP_COMMIT() asm volatile("cp.async.commit_group;" ::: "memory")
#define CP_WAIT2()  asm volatile("cp.async.wait_group 2;" ::: "memory")

__device__ __forceinline__ void mma_tf32(float& d0, float& d1, float& d2, float& d3,
                                         unsigned a0, unsigned a1, unsigned a2, unsigned a3,
                                         unsigned b0, unsigned b1) {
    asm volatile(
        "mma.sync.aligned.m16n8k8.row.col.f32.tf32.tf32.f32 "
        "{%0,%1,%2,%3}, {%4,%5,%6,%7}, {%8,%9}, {%0,%1,%2,%3};"
        : "+f"(d0), "+f"(d1), "+f"(d2), "+f"(d3)
        : "r"(a0), "r"(a1), "r"(a2), "r"(a3), "r"(b0), "r"(b1));
}

// --- staging: pure linear copies from packed image (128 threads) ---
__device__ __forceinline__ void stage1(uint32_t sb, int tid, const float* src) {
    #pragma unroll
    for (int it = 0; it < 16; it++) {
        int i = tid + it * NTHREADS;
        cpa16(sb + SM_W1 + i * 16, src + PK_W1 + i * 4);
    }
    if (tid < 16) cpa16(sb + SM_B1 + tid * 16, src + PK_B1 + tid * 4);
}
__device__ __forceinline__ void stage2(uint32_t sb, int tid, const float* src) {
    #pragma unroll
    for (int it = 0; it < 8; it++) {
        int i = tid + it * NTHREADS;
        cpa16(sb + SM_W2 + i * 16, src + PK_W2 + i * 4);
    }
    if (tid < 16) cpa16(sb + SM_B2 + tid * 16, src + PK_B2 + tid * 4);
}
__device__ __forceinline__ void stage3(uint32_t sb, int tid, const float* src) {
    #pragma unroll
    for (int it = 0; it < 16; it++) {
        int i = tid + it * NTHREADS;
        cpa16(sb + SM_W3 + i * 16, src + PK_W3 + i * 4);
    }
    if (tid < 32) cpa16(sb + SM_B3 + tid * 16, src + PK_B3 + tid * 4);
}

__global__ __launch_bounds__(NTHREADS, 2)
void expert_kernel(const float* __restrict__ state, float* __restrict__ out)
{
    extern __shared__ char smem[];
    const uint32_t sb = (uint32_t)__cvta_generic_to_shared(smem);
    const unsigned* W1u = (const unsigned*)(smem + SM_W1);
    const unsigned* W2u = (const unsigned*)(smem + SM_W2);
    const unsigned* W3u = (const unsigned*)(smem + SM_W3);
    float*    hs  = (float*)(smem + SM_H);
    const unsigned* hu = (const unsigned*)(smem + SM_H);
    const float* b1s = (const float*)(smem + SM_B1);
    const float* b2s = (const float*)(smem + SM_B2);
    const float* b3s = (const float*)(smem + SM_B3);

    const int s    = g_sperm[blockIdx.y];
    const int b0   = blockIdx.x * TB;
    const int tid  = threadIdx.x;
    const int lane = tid & 31;
    const int warp = tid >> 5;
    const int wm   = warp & 1;      // 2 warp-rows (m32)
    const int wn   = warp >> 1;     // 2 warp-cols
    const int r    = lane >> 2;
    const int q    = lane & 3;

    const int mrow0 = wm * 32 + r;

    float acc[2][8][4];
    #pragma unroll
    for (int mt = 0; mt < 2; mt++)
        #pragma unroll
        for (int nt = 0; nt < 8; nt++)
            #pragma unroll
            for (int c = 0; c < 4; c++) acc[mt][nt][c] = 0.0f;

    const int cnt = g_cnt[s];

    if (cnt > 0) {
        const float* src = g_wpack + (size_t)(s * A_ + g_list[s][0]) * PK_STRIDE;
        stage1(sb, tid, src); CP_COMMIT();
        stage2(sb, tid, src); CP_COMMIT();
        stage3(sb, tid, src); CP_COMMIT();
    }

    for (int j = 0; j < cnt; j++) {
        const int a = g_list[s][j];
        const float* srcn = (j + 1 < cnt)
            ? g_wpack + (size_t)(s * A_ + g_list[s][j + 1]) * PK_STRIDE : nullptr;

        CP_WAIT2();          // W1(j), b1(j) landed
        __syncthreads();     // publish W1; everyone done with h/W3 from prev iter

        // ---- GEMM1: h1 = relu(A @ W1 + b1), M64 N64 K128 (warp: m32 x n32) ----
        {
            float d[2][4][4];
            #pragma unroll
            for (int mt = 0; mt < 2; mt++)
                #pragma unroll
                for (int nt = 0; nt < 4; nt++)
                    { d[mt][nt][0]=0; d[mt][nt][1]=0; d[mt][nt][2]=0; d[mt][nt][3]=0; }

            const unsigned* atile =
                g_apack + ((size_t)(blockIdx.x * 2 + wm) * A_ + a) * 4096;

            #pragma unroll 4
            for (int kc = 0; kc < 16; kc++) {
                uint4 A0 = *(const uint4*)(atile + ((kc * 2 + 0) * 32 + lane) * 4);
                uint4 A1 = *(const uint4*)(atile + ((kc * 2 + 1) * 32 + lane) * 4);
                uint4 p0 = *(const uint4*)(W1u + ((kc * 4 + wn * 2 + 0) * 32 + lane) * 4);
                uint4 p1 = *(const uint4*)(W1u + ((kc * 4 + wn * 2 + 1) * 32 + lane) * 4);
                unsigned bf[4][2];
                bf[0][0] = p0.x; bf[0][1] = p0.y; bf[1][0] = p0.z; bf[1][1] = p0.w;
                bf[2][0] = p1.x; bf[2][1] = p1.y; bf[3][0] = p1.z; bf[3][1] = p1.w;
                #pragma unroll
                for (int nt = 0; nt < 4; nt++) {
                    mma_tf32(d[0][nt][0], d[0][nt][1], d[0][nt][2], d[0][nt][3],
                             A0.x, A0.y, A0.z, A0.w, bf[nt][0], bf[nt][1]);
                    mma_tf32(d[1][nt][0], d[1][nt][1], d[1][nt][2], d[1][nt][3],
                             A1.x, A1.y, A1.z, A1.w, bf[nt][0], bf[nt][1]);
                }
            }
            #pragma unroll
            for (int mt = 0; mt < 2; mt++)
                #pragma unroll
                for (int nt = 0; nt < 4; nt++) {
                    int col = wn * 32 + nt * 8 + 2 * q;
                    float bb0 = b1s[col], bb1 = b1s[col + 1];
                    int row = mrow0 + mt * 16;
                    uint2 v0 = { f2tf(fmaxf(d[mt][nt][0] + bb0, 0.0f)),
                                 f2tf(fmaxf(d[mt][nt][1] + bb1, 0.0f)) };
                    uint2 v1 = { f2tf(fmaxf(d[mt][nt][2] + bb0, 0.0f)),
                                 f2tf(fmaxf(d[mt][nt][3] + bb1, 0.0f)) };
                    *(uint2*)(hs + row * H_LD + col)       = v0;
                    *(uint2*)(hs + (row + 8) * H_LD + col) = v1;
                }
        }
        __syncthreads();     // ALL warps done reading W1(j)/b1(j) before overwrite
        if (srcn) { stage1(sb, tid, srcn); }
        CP_COMMIT();
        CP_WAIT2();          // W2(j), b2(j) landed
        __syncthreads();     // publish W2; h1 visible to all warps

        // ---- GEMM2: h2 = relu(h1 @ W2 + b2), M64 N64 K64 (in-place h) ----
        {
            unsigned a2r[8][2][4];
            #pragma unroll
            for (int kc = 0; kc < 8; kc++) {
                const int k0 = kc * 8;
                #pragma unroll
                for (int mt = 0; mt < 2; mt++) {
                    const unsigned* hb = hu + (mrow0 + mt * 16) * H_LD + k0 + q;
                    a2r[kc][mt][0] = hb[0];
                    a2r[kc][mt][1] = hb[8 * H_LD];
                    a2r[kc][mt][2] = hb[4];
                    a2r[kc][mt][3] = hb[8 * H_LD + 4];
                }
            }
            __syncthreads();   // all reads of h1 done; safe to overwrite

            float d[2][4][4];
            #pragma unroll
            for (int mt = 0; mt < 2; mt++)
                #pragma unroll
                for (int nt = 0; nt < 4; nt++)
                    { d[mt][nt][0]=0; d[mt][nt][1]=0; d[mt][nt][2]=0; d[mt][nt][3]=0; }
            #pragma unroll
            for (int kc = 0; kc < 8; kc++) {
                unsigned bf[4][2];
                uint4 p0 = *(const uint4*)(W2u + ((kc * 4 + wn * 2 + 0) * 32 + lane) * 4);
                uint4 p1 = *(const uint4*)(W2u + ((kc * 4 + wn * 2 + 1) * 32 + lane) * 4);
                bf[0][0] = p0.x; bf[0][1] = p0.y; bf[1][0] = p0.z; bf[1][1] = p0.w;
                bf[2][0] = p1.x; bf[2][1] = p1.y; bf[3][0] = p1.z; bf[3][1] = p1.w;
                #pragma unroll
                for (int mt = 0; mt < 2; mt++)
                    #pragma unroll
                    for (int nt = 0; nt < 4; nt++)
                        mma_tf32(d[mt][nt][0], d[mt][nt][1], d[mt][nt][2], d[mt][nt][3],
                                 a2r[kc][mt][0], a2r[kc][mt][1], a2r[kc][mt][2], a2r[kc][mt][3],
                                 bf[nt][0], bf[nt][1]);
            }
            #pragma unroll
            for (int mt = 0; mt < 2; mt++)
                #pragma unroll
                for (int nt = 0; nt < 4; nt++) {
                    int col = wn * 32 + nt * 8 + 2 * q;
                    float bb0 = b2s[col], bb1 = b2s[col + 1];
                    int row = mrow0 + mt * 16;
                    uint2 v0 = { f2tf(fmaxf(d[mt][nt][0] + bb0, 0.0f)),
                                 f2tf(fmaxf(d[mt][nt][1] + bb1, 0.0f)) };
                    uint2 v1 = { f2tf(fmaxf(d[mt][nt][2] + bb0, 0.0f)),
                                 f2tf(fmaxf(d[mt][nt][3] + bb1, 0.0f)) };
                    *(uint2*)(hs + row * H_LD + col)       = v0;
                    *(uint2*)(hs + (row + 8) * H_LD + col) = v1;
                }
        }
        __syncthreads();     // ALL warps done reading W2(j)/b2(j) before overwrite
        if (srcn) { stage2(sb, tid, srcn); }
        CP_COMMIT();
        CP_WAIT2();          // W3(j), b3(j) landed
        __syncthreads();     // publish W3; h2 visible to all warps

        // ---- GEMM3: acc += relu(h2 @ W3 + b3), M64 N128 K64 (warp: m32 x n64) ----
        {
            float d[2][8][4];
            #pragma unroll
            for (int mt = 0; mt < 2; mt++)
                #pragma unroll
                for (int nt = 0; nt < 8; nt++)
                    { d[mt][nt][0]=0; d[mt][nt][1]=0; d[mt][nt][2]=0; d[mt][nt][3]=0; }
            #pragma unroll 2
            for (int kc = 0; kc < 8; kc++) {
                const int k0 = kc * 8;
                unsigned af[2][4], bf[8][2];
                #pragma unroll
                for (int mt = 0; mt < 2; mt++) {
                    const unsigned* hb = hu + (mrow0 + mt * 16) * H_LD + k0 + q;
                    af[mt][0] = hb[0];
                    af[mt][1] = hb[8 * H_LD];
                    af[mt][2] = hb[4];
                    af[mt][3] = hb[8 * H_LD + 4];
                }
                #pragma unroll
                for (int pp = 0; pp < 4; pp++) {
                    uint4 p = *(const uint4*)(W3u + ((kc * 8 + wn * 4 + pp) * 32 + lane) * 4);
                    bf[2 * pp][0]     = p.x; bf[2 * pp][1]     = p.y;
                    bf[2 * pp + 1][0] = p.z; bf[2 * pp + 1][1] = p.w;
                }
                #pragma unroll
                for (int mt = 0; mt < 2; mt++)
                    #pragma unroll
                    for (int nt = 0; nt < 8; nt++)
                        mma_tf32(d[mt][nt][0], d[mt][nt][1], d[mt][nt][2], d[mt][nt][3],
                                 af[mt][0], af[mt][1], af[mt][2], af[mt][3],
                                 bf[nt][0], bf[nt][1]);
            }
            #pragma unroll
            for (int mt = 0; mt < 2; mt++)
                #pragma unroll
                for (int nt = 0; nt < 8; nt++) {
                    int col = wn * 64 + nt * 8 + 2 * q;
                    float bb0 = b3s[col], bb1 = b3s[col + 1];
                    acc[mt][nt][0] += fmaxf(d[mt][nt][0] + bb0, 0.0f);
                    acc[mt][nt][1] += fmaxf(d[mt][nt][1] + bb1, 0.0f);
                    acc[mt][nt][2] += fmaxf(d[mt][nt][2] + bb0, 0.0f);
                    acc[mt][nt][3] += fmaxf(d[mt][nt][3] + bb1, 0.0f);
                }
        }
        __syncthreads();     // ALL warps done reading W3(j)/b3(j)/h2 before overwrite
        if (srcn) { stage3(sb, tid, srcn); }
        CP_COMMIT();
    }

    // ---- epilogue: out = state + diff ----
    #pragma unroll
    for (int mt = 0; mt < 2; mt++)
        #pragma unroll
        for (int nt = 0; nt < 8; nt++) {
            int row = b0 + mrow0 + mt * 16;
            int col = wn * 64 + nt * 8 + 2 * q;
            size_t base = ((size_t)row * S_ + s) * DS_ + col;
            float2 s0 = *(const float2*)(state + base);
            float2 s1 = *(const float2*)(state + base + 8 * (size_t)S_ * DS_);
            float2 o0 = { s0.x + acc[mt][nt][0], s0.y + acc[mt][nt][1] };
            float2 o1 = { s1.x + acc[mt][nt][2], s1.y + acc[mt][nt][3] };
            *(float2*)(out + base)                        = o0;
            *(float2*)(out + base + 8 * (size_t)S_ * DS_) = o1;
        }
}

extern "C" void kernel_launch(void* const* d_in, const int* in_sizes, int n_in,
                              void* d_out, int out_size)
{
    const float* state = (const float*)d_in[0];
    const float* act   = (const float*)d_in[1];
    const void*  rel   = d_in[2];
    const float* W1 = (const float*)d_in[3];
    const float* b1 = (const float*)d_in[4];
    const float* W2 = (const float*)d_in[5];
    const float* b2 = (const float*)d_in[6];
    const float* W3 = (const float*)d_in[7];
    const float* b3 = (const float*)d_in[8];
    float* out = (float*)d_out;

    const int B = in_sizes[0] / (S_ * DS_);

    cudaFuncSetAttribute(expert_kernel,
                         cudaFuncAttributeMaxDynamicSharedMemorySize, SMEM_BYTES);

    prep_mask_kernel<<<1, 32>>>((const unsigned*)rel);
    prep_pack<<<256 + (B / 32) * A_, 256>>>(W1, b1, W2, b2, W3, b3, act);

    dim3 grid(B / TB, S_);
    expert_kernel<<<grid, NTHREADS, SMEM_BYTES>>>(state, out);
}

// round 12
// speedup vs baseline: 2.1585x; 1.0204x over previous
#include <cuda_runtime.h>
#include <cstdint>

#define S_  16
#define A_  16
#define DA_ 128
#define DS_ 128
#define H_  64
#define TB  64
#define NTHREADS 128
#define B_MAX 2048

#define H_LD 68

// packed expert image (word offsets)
#define PK_W1 0
#define PK_W2 8192
#define PK_W3 12288
#define PK_B1 20480
#define PK_B2 20544
#define PK_B3 20608
#define PK_STRIDE 20736

// SMEM byte offsets
#define SM_W1 0
#define SM_W2 32768
#define SM_W3 49152
#define SM_H  81920
#define SM_B1 99328
#define SM_B2 99584
#define SM_B3 99840
#define SMEM_BYTES 100352

__device__ int g_cnt[S_];
__device__ int g_list[S_][A_];
__device__ int g_sperm[S_];
__device__ float    g_wpack[256 * PK_STRIDE];
__device__ unsigned g_apack[(size_t)B_MAX * A_ * DA_];   // fragment-packed A tiles

// Parallelized mask prep: parallel global loads (the 17.7us serial version was
// pure DRAM-latency), serial-but-shared compaction.
__global__ void prep_mask_kernel(const unsigned* __restrict__ rel) {
    __shared__ unsigned sv[64];
    __shared__ int sm_[S_ * A_];
    __shared__ int flags[2];
    const int tid = threadIdx.x;

    if (tid < 64) sv[tid] = rel[tid];     // 256 B: safe for all dtype interpretations
    __syncthreads();
    if (tid == 0) {
        bool allint = true, allfloat = true;
        for (int i = 0; i < 64; i++) {
            unsigned u = sv[i];
            if (u > 1u) allint = false;
            if (!(u == 0u || u == 0x3F800000u)) allfloat = false;
        }
        flags[0] = allint; flags[1] = allfloat;
    }
    __syncthreads();

    if (flags[0]) {
        if (tid < S_ * A_) sm_[tid] = (((const int*)rel)[tid] != 0);
    } else if (flags[1]) {
        if (tid < S_ * A_) sm_[tid] = (((const float*)rel)[tid] != 0.0f);
    } else {
        if (tid < 64) {
            unsigned u = sv[tid];
            sm_[tid * 4 + 0] = ((u      ) & 0xFF) != 0;
            sm_[tid * 4 + 1] = ((u >>  8) & 0xFF) != 0;
            sm_[tid * 4 + 2] = ((u >> 16) & 0xFF) != 0;
            sm_[tid * 4 + 3] = ((u >> 24) & 0xFF) != 0;
        }
    }
    __syncthreads();

    if (tid == 0) {
        int cnt[S_];
        for (int s = 0; s < S_; s++) {
            int c = 0;
            for (int a = 0; a < A_; a++)
                if (sm_[s * A_ + a]) g_list[s][c++] = a;
            g_cnt[s] = c;
            cnt[s] = c;
        }
        int perm[S_];
        for (int i = 0; i < S_; i++) perm[i] = i;
        for (int i = 0; i < S_ - 1; i++) {
            int best = i;
            for (int j = i + 1; j < S_; j++)
                if (cnt[perm[j]] > cnt[perm[best]]) best = j;
            int t = perm[i]; perm[i] = perm[best]; perm[best] = t;
        }
        for (int i = 0; i < S_; i++) g_sperm[i] = perm[i];
    }
}

__device__ __forceinline__ unsigned f2tf(float f) {
    unsigned u;
    asm("cvt.rna.tf32.f32 %0, %1;" : "=r"(u) : "f"(f));
    return u;
}

// One merged pack kernel.
// Blocks [0,256): weight fragment packing (coalesced via SMEM staging).
// Blocks [256, 256 + nmb*A_): A fragment packing per (mblock32, a) tile.
// A tile layout (uint4 cells): cell = (kc*2 + mt)*32 + lane
//   r=lane>>2, q=lane&3, rl=mt*16+r, k=kc*8+q:
//   u = { A[rl][k], A[rl+8][k], A[rl][k+4], A[rl+8][k+4] }   (matches af[mt][0..3])
__global__ void prep_pack(const float* __restrict__ W1, const float* __restrict__ b1,
                          const float* __restrict__ W2, const float* __restrict__ b2,
                          const float* __restrict__ W3, const float* __restrict__ b3,
                          const float* __restrict__ act) {
    __shared__ float sbuf[8192];
    const int bx = blockIdx.x;
    const int tid = threadIdx.x;

    if (bx < 256) {
        const int e = bx;
        float* dst = g_wpack + (size_t)e * PK_STRIDE;
        // ---- W1: K=128 x N=64, NP=4 ----
        {
            const float4* s = (const float4*)(W1 + (size_t)e * (DA_ * H_));
            for (int i = tid; i < 2048; i += 256) ((float4*)sbuf)[i] = s[i];
            __syncthreads();
            for (int cell = tid; cell < 2048; cell += 256) {
                int lane = cell & 31, g = cell >> 5;
                int kc = g >> 2, np = g & 3;
                int kb = kc * 8 + (lane & 3), nb = np * 16 + (lane >> 2);
                uint4 u;
                u.x = f2tf(sbuf[(kb + 0) * 64 + nb]);
                u.y = f2tf(sbuf[(kb + 4) * 64 + nb]);
                u.z = f2tf(sbuf[(kb + 0) * 64 + nb + 8]);
                u.w = f2tf(sbuf[(kb + 4) * 64 + nb + 8]);
                ((uint4*)(dst + PK_W1))[cell] = u;
            }
            __syncthreads();
        }
        // ---- W2: K=64 x N=64, NP=4 ----
        {
            const float4* s = (const float4*)(W2 + (size_t)e * (H_ * H_));
            for (int i = tid; i < 1024; i += 256) ((float4*)sbuf)[i] = s[i];
            __syncthreads();
            for (int cell = tid; cell < 1024; cell += 256) {
                int lane = cell & 31, g = cell >> 5;
                int kc = g >> 2, np = g & 3;
                int kb = kc * 8 + (lane & 3), nb = np * 16 + (lane >> 2);
                uint4 u;
                u.x = f2tf(sbuf[(kb + 0) * 64 + nb]);
                u.y = f2tf(sbuf[(kb + 4) * 64 + nb]);
                u.z = f2tf(sbuf[(kb + 0) * 64 + nb + 8]);
                u.w = f2tf(sbuf[(kb + 4) * 64 + nb + 8]);
                ((uint4*)(dst + PK_W2))[cell] = u;
            }
            __syncthreads();
        }
        // ---- W3: K=64 x N=128, NP=8 ----
        {
            const float4* s = (const float4*)(W3 + (size_t)e * (H_ * DS_));
            for (int i = tid; i < 2048; i += 256) ((float4*)sbuf)[i] = s[i];
            __syncthreads();
            for (int cell = tid; cell < 2048; cell += 256) {
                int lane = cell & 31, g = cell >> 5;
                int kc = g >> 3, np = g & 7;
                int kb = kc * 8 + (lane & 3), nb = np * 16 + (lane >> 2);
                uint4 u;
                u.x = f2tf(sbuf[(kb + 0) * 128 + nb]);
                u.y = f2tf(sbuf[(kb + 4) * 128 + nb]);
                u.z = f2tf(sbuf[(kb + 0) * 128 + nb + 8]);
                u.w = f2tf(sbuf[(kb + 4) * 128 + nb + 8]);
                ((uint4*)(dst + PK_W3))[cell] = u;
            }
        }
        if (tid < 64)        dst[PK_B1 + tid]        = b1[e * H_  + tid];
        else if (tid < 128)  dst[PK_B2 + tid - 64]   = b2[e * H_  + tid - 64];
        else if (tid < 256)  dst[PK_B3 + tid - 128]  = b3[e * DS_ + tid - 128];
    } else {
        const int t = bx - 256;
        const int mb = t >> 4, a = t & 15;
        const float* srcb = act + ((size_t)(mb * 32) * A_ + a) * DA_;
        for (int i = tid; i < 1024; i += 256) {
            int row = i >> 5, c4 = i & 31;
            *(float4*)(sbuf + row * 128 + c4 * 4) =
                *(const float4*)(srcb + (size_t)row * A_ * DA_ + c4 * 4);
        }
        __syncthreads();
        unsigned* dst = g_apack + ((size_t)mb * A_ + a) * 4096;
        for (int cell = tid; cell < 1024; cell += 256) {
            int lane = cell & 31, mt = (cell >> 5) & 1, kc = cell >> 6;
            int rl = mt * 16 + (lane >> 2), k = kc * 8 + (lane & 3);
            uint4 u;
            u.x = f2tf(sbuf[rl * 128 + k]);
            u.y = f2tf(sbuf[(rl + 8) * 128 + k]);
            u.z = f2tf(sbuf[rl * 128 + k + 4]);
            u.w = f2tf(sbuf[(rl + 8) * 128 + k + 4]);
            ((uint4*)dst)[cell] = u;
        }
    }
}

__device__ __forceinline__ void cpa16(uint32_t dst, const void* src) {
    asm volatile("cp.async.cg.shared.global [%0], [%1], 16;" :: "r"(dst), "l"(src));
}
#define CP_COMMIT() asm volatile("cp.async.commit_group;" ::: "memory")
#define CP_WAIT2()  asm volatile("cp.async.wait_group 2;" ::: "memory")

__device__ __forceinline__ void mma_tf32(float& d0, float& d1, float& d2, float& d3,
                                         unsigned a0, unsigned a1, unsigned a2, unsigned a3,
                                         unsigned b0, unsigned b1) {
    asm volatile(
        "mma.sync.aligned.m16n8k8.row.col.f32.tf32.tf32.f32 "
        "{%0,%1,%2,%3}, {%4,%5,%6,%7}, {%8,%9}, {%0,%1,%2,%3};"
        : "+f"(d0), "+f"(d1), "+f"(d2), "+f"(d3)
        : "r"(a0), "r"(a1), "r"(a2), "r"(a3), "r"(b0), "r"(b1));
}

// --- staging: pure linear copies from packed image (128 threads) ---
__device__ __forceinline__ void stage1(uint32_t sb, int tid, const float* src) {
    #pragma unroll
    for (int it = 0; it < 16; it++) {
        int i = tid + it * NTHREADS;
        cpa16(sb + SM_W1 + i * 16, src + PK_W1 + i * 4);
    }
    if (tid < 16) cpa16(sb + SM_B1 + tid * 16, src + PK_B1 + tid * 4);
}
__device__ __forceinline__ void stage2(uint32_t sb, int tid, const float* src) {
    #pragma unroll
    for (int it = 0; it < 8; it++) {
        int i = tid + it * NTHREADS;
        cpa16(sb + SM_W2 + i * 16, src + PK_W2 + i * 4);
    }
    if (tid < 16) cpa16(sb + SM_B2 + tid * 16, src + PK_B2 + tid * 4);
}
__device__ __forceinline__ void stage3(uint32_t sb, int tid, const float* src) {
    #pragma unroll
    for (int it = 0; it < 16; it++) {
        int i = tid + it * NTHREADS;
        cpa16(sb + SM_W3 + i * 16, src + PK_W3 + i * 4);
    }
    if (tid < 32) cpa16(sb + SM_B3 + tid * 16, src + PK_B3 + tid * 4);
}

__global__ __launch_bounds__(NTHREADS, 2)
void expert_kernel(const float* __restrict__ state, float* __restrict__ out)
{
    extern __shared__ char smem[];
    const uint32_t sb = (uint32_t)__cvta_generic_to_shared(smem);
    const unsigned* W1u = (const unsigned*)(smem + SM_W1);
    const unsigned* W2u = (const unsigned*)(smem + SM_W2);
    const unsigned* W3u = (const unsigned*)(smem + SM_W3);
    float*    hs  = (float*)(smem + SM_H);
    const unsigned* hu = (const unsigned*)(smem + SM_H);
    const float* b1s = (const float*)(smem + SM_B1);
    const float* b2s = (const float*)(smem + SM_B2);
    const float* b3s = (const float*)(smem + SM_B3);

    const int s    = g_sperm[blockIdx.y];
    const int b0   = blockIdx.x * TB;
    const int tid  = threadIdx.x;
    const int lane = tid & 31;
    const int warp = tid >> 5;
    const int wm   = warp & 1;      // 2 warp-rows (m32)
    const int wn   = warp >> 1;     // 2 warp-cols
    const int r    = lane >> 2;
    const int q    = lane & 3;

    const int mrow0 = wm * 32 + r;

    float acc[2][8][4];
    #pragma unroll
    for (int mt = 0; mt < 2; mt++)
        #pragma unroll
        for (int nt = 0; nt < 8; nt++)
            #pragma unroll
            for (int c = 0; c < 4; c++) acc[mt][nt][c] = 0.0f;

    const int cnt = g_cnt[s];

    if (cnt > 0) {
        const float* src = g_wpack + (size_t)(s * A_ + g_list[s][0]) * PK_STRIDE;
        stage1(sb, tid, src); CP_COMMIT();
        stage2(sb, tid, src); CP_COMMIT();
        stage3(sb, tid, src); CP_COMMIT();
    }

    for (int j = 0; j < cnt; j++) {
        const int a = g_list[s][j];
        const float* srcn = (j + 1 < cnt)
            ? g_wpack + (size_t)(s * A_ + g_list[s][j + 1]) * PK_STRIDE : nullptr;

        CP_WAIT2();          // W1(j), b1(j) landed
        __syncthreads();     // publish W1; everyone done with h/W3 from prev iter

        // ---- GEMM1: h1 = relu(A @ W1 + b1), M64 N64 K128 (warp: m32 x n32) ----
        {
            float d[2][4][4];
            #pragma unroll
            for (int mt = 0; mt < 2; mt++)
                #pragma unroll
                for (int nt = 0; nt < 4; nt++)
                    { d[mt][nt][0]=0; d[mt][nt][1]=0; d[mt][nt][2]=0; d[mt][nt][3]=0; }

            const unsigned* atile =
                g_apack + ((size_t)(blockIdx.x * 2 + wm) * A_ + a) * 4096;

            #pragma unroll 4
            for (int kc = 0; kc < 16; kc++) {
                uint4 A0 = *(const uint4*)(atile + ((kc * 2 + 0) * 32 + lane) * 4);
                uint4 A1 = *(const uint4*)(atile + ((kc * 2 + 1) * 32 + lane) * 4);
                uint4 p0 = *(const uint4*)(W1u + ((kc * 4 + wn * 2 + 0) * 32 + lane) * 4);
                uint4 p1 = *(const uint4*)(W1u + ((kc * 4 + wn * 2 + 1) * 32 + lane) * 4);
                unsigned bf[4][2];
                bf[0][0] = p0.x; bf[0][1] = p0.y; bf[1][0] = p0.z; bf[1][1] = p0.w;
                bf[2][0] = p1.x; bf[2][1] = p1.y; bf[3][0] = p1.z; bf[3][1] = p1.w;
                #pragma unroll
                for (int nt = 0; nt < 4; nt++) {
                    mma_tf32(d[0][nt][0], d[0][nt][1], d[0][nt][2], d[0][nt][3],
                             A0.x, A0.y, A0.z, A0.w, bf[nt][0], bf[nt][1]);
                    mma_tf32(d[1][nt][0], d[1][nt][1], d[1][nt][2], d[1][nt][3],
                             A1.x, A1.y, A1.z, A1.w, bf[nt][0], bf[nt][1]);
                }
            }
            #pragma unroll
            for (int mt = 0; mt < 2; mt++)
                #pragma unroll
                for (int nt = 0; nt < 4; nt++) {
                    int col = wn * 32 + nt * 8 + 2 * q;
                    float bb0 = b1s[col], bb1 = b1s[col + 1];
                    int row = mrow0 + mt * 16;
                    uint2 v0 = { f2tf(fmaxf(d[mt][nt][0] + bb0, 0.0f)),
                                 f2tf(fmaxf(d[mt][nt][1] + bb1, 0.0f)) };
                    uint2 v1 = { f2tf(fmaxf(d[mt][nt][2] + bb0, 0.0f)),
                                 f2tf(fmaxf(d[mt][nt][3] + bb1, 0.0f)) };
                    *(uint2*)(hs + row * H_LD + col)       = v0;
                    *(uint2*)(hs + (row + 8) * H_LD + col) = v1;
                }
        }
        __syncthreads();     // ALL warps done reading W1(j)/b1(j) before overwrite
        if (srcn) { stage1(sb, tid, srcn); }
        CP_COMMIT();
        CP_WAIT2();          // W2(j), b2(j) landed
        __syncthreads();     // publish W2; h1 visible to all warps

        // ---- GEMM2: h2 = relu(h1 @ W2 + b2), M64 N64 K64 (in-place h) ----
        {
            unsigned a2r[8][2][4];
            #pragma unroll
            for (int kc = 0; kc < 8; kc++) {
                const int k0 = kc * 8;
                #pragma unroll
                for (int mt = 0; mt < 2; mt++) {
                    const unsigned* hb = hu + (mrow0 + mt * 16) * H_LD + k0 + q;
                    a2r[kc][mt][0] = hb[0];
                    a2r[kc][mt][1] = hb[8 * H_LD];
                    a2r[kc][mt][2] = hb[4];
                    a2r[kc][mt][3] = hb[8 * H_LD + 4];
                }
            }
            __syncthreads();   // all reads of h1 done; safe to overwrite

            float d[2][4][4];
            #pragma unroll
            for (int mt = 0; mt < 2; mt++)
                #pragma unroll
                for (int nt = 0; nt < 4; nt++)
                    { d[mt][nt][0]=0; d[mt][nt][1]=0; d[mt][nt][2]=0; d[mt][nt][3]=0; }
            #pragma unroll
            for (int kc = 0; kc < 8; kc++) {
                unsigned bf[4][2];
                uint4 p0 = *(const uint4*)(W2u + ((kc * 4 + wn * 2 + 0) * 32 + lane) * 4);
                uint4 p1 = *(const uint4*)(W2u + ((kc * 4 + wn * 2 + 1) * 32 + lane) * 4);
                bf[0][0] = p0.x; bf[0][1] = p0.y; bf[1][0] = p0.z; bf[1][1] = p0.w;
                bf[2][0] = p1.x; bf[2][1] = p1.y; bf[3][0] = p1.z; bf[3][1] = p1.w;
                #pragma unroll
                for (int mt = 0; mt < 2; mt++)
                    #pragma unroll
                    for (int nt = 0; nt < 4; nt++)
                        mma_tf32(d[mt][nt][0], d[mt][nt][1], d[mt][nt][2], d[mt][nt][3],
                                 a2r[kc][mt][0], a2r[kc][mt][1], a2r[kc][mt][2], a2r[kc][mt][3],
                                 bf[nt][0], bf[nt][1]);
            }
            #pragma unroll
            for (int mt = 0; mt < 2; mt++)
                #pragma unroll
                for (int nt = 0; nt < 4; nt++) {
                    int col = wn * 32 + nt * 8 + 2 * q;
                    float bb0 = b2s[col], bb1 = b2s[col + 1];
                    int row = mrow0 + mt * 16;
                    uint2 v0 = { f2tf(fmaxf(d[mt][nt][0] + bb0, 0.0f)),
                                 f2tf(fmaxf(d[mt][nt][1] + bb1, 0.0f)) };
                    uint2 v1 = { f2tf(fmaxf(d[mt][nt][2] + bb0, 0.0f)),
                                 f2tf(fmaxf(d[mt][nt][3] + bb1, 0.0f)) };
                    *(uint2*)(hs + row * H_LD + col)       = v0;
                    *(uint2*)(hs + (row + 8) * H_LD + col) = v1;
                }
        }
        __syncthreads();     // ALL warps done reading W2(j)/b2(j) before overwrite
        if (srcn) { stage2(sb, tid, srcn); }
        CP_COMMIT();
        CP_WAIT2();          // W3(j), b3(j) landed
        __syncthreads();     // publish W3; h2 visible to all warps

        // ---- GEMM3: acc += relu(h2 @ W3 + b3), M64 N128 K64 (warp: m32 x n64) ----
        {
            float d[2][8][4];
            #pragma unroll
            for (int mt = 0; mt < 2; mt++)
                #pragma unroll
                for (int nt = 0; nt < 8; nt++)
                    { d[mt][nt][0]=0; d[mt][nt][1]=0; d[mt][nt][2]=0; d[mt][nt][3]=0; }
            #pragma unroll 2
            for (int kc = 0; kc < 8; kc++) {
                const int k0 = kc * 8;
                unsigned af[2][4], bf[8][2];
                #pragma unroll
                for (int mt = 0; mt < 2; mt++) {
                    const unsigned* hb = hu + (mrow0 + mt * 16) * H_LD + k0 + q;
                    af[mt][0] = hb[0];
                    af[mt][1] = hb[8 * H_LD];
                    af[mt][2] = hb[4];
                    af[mt][3] = hb[8 * H_LD + 4];
                }
                #pragma unroll
                for (int pp = 0; pp < 4; pp++) {
                    uint4 p = *(const uint4*)(W3u + ((kc * 8 + wn * 4 + pp) * 32 + lane) * 4);
                    bf[2 * pp][0]     = p.x; bf[2 * pp][1]     = p.y;
                    bf[2 * pp + 1][0] = p.z; bf[2 * pp + 1][1] = p.w;
                }
                #pragma unroll
                for (int mt = 0; mt < 2; mt++)
                    #pragma unroll
                    for (int nt = 0; nt < 8; nt++)
                        mma_tf32(d[mt][nt][0], d[mt][nt][1], d[mt][nt][2], d[mt][nt][3],
                                 af[mt][0], af[mt][1], af[mt][2], af[mt][3],
                                 bf[nt][0], bf[nt][1]);
            }
            #pragma unroll
            for (int mt = 0; mt < 2; mt++)
                #pragma unroll
                for (int nt = 0; nt < 8; nt++) {
                    int col = wn * 64 + nt * 8 + 2 * q;
                    float bb0 = b3s[col], bb1 = b3s[col + 1];
                    acc[mt][nt][0] += fmaxf(d[mt][nt][0] + bb0, 0.0f);
                    acc[mt][nt][1] += fmaxf(d[mt][nt][1] + bb1, 0.0f);
                    acc[mt][nt][2] += fmaxf(d[mt][nt][2] + bb0, 0.0f);
                    acc[mt][nt][3] += fmaxf(d[mt][nt][3] + bb1, 0.0f);
                }
        }
        __syncthreads();     // ALL warps done reading W3(j)/b3(j)/h2 before overwrite
        if (srcn) { stage3(sb, tid, srcn); }
        CP_COMMIT();
    }

    // ---- epilogue: out = state + diff ----
    #pragma unroll
    for (int mt = 0; mt < 2; mt++)
        #pragma unroll
        for (int nt = 0; nt < 8; nt++) {
            int row = b0 + mrow0 + mt * 16;
            int col = wn * 64 + nt * 8 + 2 * q;
            size_t base = ((size_t)row * S_ + s) * DS_ + col;
            float2 s0 = *(const float2*)(state + base);
            float2 s1 = *(const float2*)(state + base + 8 * (size_t)S_ * DS_);
            float2 o0 = { s0.x + acc[mt][nt][0], s0.y + acc[mt][nt][1] };
            float2 o1 = { s1.x + acc[mt][nt][2], s1.y + acc[mt][nt][3] };
            *(float2*)(out + base)                        = o0;
            *(float2*)(out + base + 8 * (size_t)S_ * DS_) = o1;
        }
}

extern "C" void kernel_launch(void* const* d_in, const int* in_sizes, int n_in,
                              void* d_out, int out_size)
{
    const float* state = (const float*)d_in[0];
    const float* act   = (const float*)d_in[1];
    const void*  rel   = d_in[2];
    const float* W1 = (const float*)d_in[3];
    const float* b1 = (const float*)d_in[4];
    const float* W2 = (const float*)d_in[5];
    const float* b2 = (const float*)d_in[6];
    const float* W3 = (const float*)d_in[7];
    const float* b3 = (const float*)d_in[8];
    float* out = (float*)d_out;

    const int B = in_sizes[0] / (S_ * DS_);

    cudaFuncSetAttribute(expert_kernel,
                         cudaFuncAttributeMaxDynamicSharedMemorySize, SMEM_BYTES);

    prep_mask_kernel<<<1, 256>>>((const unsigned*)rel);
    prep_pack<<<256 + (B / 32) * A_, 256>>>(W1, b1, W2, b2, W3, b3, act);

    dim3 grid(B / TB, S_);
    expert_kernel<<<grid, NTHREADS, SMEM_BYTES>>>(state, out);
}